// round 6
// baseline (speedup 1.0000x reference)
#include <cuda_runtime.h>
#include <cuda_bf16.h>

#define FULL 0xffffffffu

static constexpr int S = 256, Dm = 64;
static constexpr int STR1 = 269;            // padded emb row: 6 + 256 + 6 (+1 spare)
static constexpr int L1_LEN = 262, K1 = 131;
static constexpr int STR2 = 140;            // padded A row: 4 + 131 + 4 (+1 spare)
static constexpr int L2_LEN = 135, K2 = 4;
static constexpr int NTHREADS = 512;
static constexpr int NW = NTHREADS / 32;    // 16 warps

static constexpr int OFF_IN = 0;                      // 64*269 floats
static constexpr int OFF_A  = 64 * STR1;              // 256*140 floats
static constexpr int OFF_T2 = OFF_A + 256 * STR2;     // 1024 floats
static constexpr int OFF_W  = OFF_T2 + 1024;          // 16*88 floats
static constexpr int SMEM_FLOATS = OFF_W + NW * 88;
static constexpr int SMEM_BYTES  = SMEM_FLOATS * 4;   // ~222 KB (< 227KB opt-in)
static constexpr int ZERO_FLOATS = OFF_T2;            // zero sm_in + sm_A (pads!)

// Monotone float -> uint key (total order, -inf smallest)
__device__ __forceinline__ unsigned fkey(float f) {
    unsigned b = __float_as_uint(f);
    return (b & 0x80000000u) ? ~b : (b | 0x80000000u);
}

__device__ __forceinline__ int iscan(int v, int lane) {
#pragma unroll
    for (int d = 1; d < 32; d <<= 1) {
        int n = __shfl_up_sync(FULL, v, d);
        if (lane >= d) v += n;
    }
    return v;
}

// Warp-collective, order-preserving top-k select of the values held blocked
// across lanes (lane l holds NV consecutive positions). Invalid slots must be
// -inf. Writes exactly k values (tanh applied) in original index order.
// Semantics match jax.lax.top_k (ties broken by lowest index) + sorted idx.
template <int NV>
__device__ __forceinline__ void topk_write(const float* v, int k, float* outrow, int lane) {
    unsigned u[NV];
#pragma unroll
    for (int j = 0; j < NV; j++) u[j] = fkey(v[j]);

    // 32-step radix bisection: largest T with count(u >= T) >= k == k-th largest key
    unsigned thr = 0;
#pragma unroll 1
    for (int bit = 31; bit >= 0; --bit) {
        unsigned cand = thr | (1u << bit);
        int c = 0;
#pragma unroll
        for (int j = 0; j < NV; j++) c += (u[j] >= cand);
        c = __reduce_add_sync(FULL, c);
        if (c >= k) thr = cand;
    }

    int gt = 0, eq = 0;
#pragma unroll
    for (int j = 0; j < NV; j++) { gt += (u[j] > thr); eq += (u[j] == thr); }
    int gt_tot = __reduce_add_sync(FULL, gt);
    int extra = k - gt_tot;                       // ties to keep (earliest-index)
    int eq_excl = iscan(eq, lane) - eq;
    int myq = extra - eq_excl;
    myq = myq < 0 ? 0 : (myq > eq ? eq : myq);
    int kc = gt + myq;
    int pos = iscan(kc, lane) - kc;               // ordered compaction offset
    int used = 0;
#pragma unroll
    for (int j = 0; j < NV; j++) {
        bool keep = (u[j] > thr);
        if (!keep && u[j] == thr && used < myq) { keep = true; used++; }
        if (keep) outrow[pos++] = tanhf(v[j]);
    }
}

__global__ void __launch_bounds__(NTHREADS, 1) dcnn_kernel(
    const int* __restrict__ x, const float* __restrict__ emb,
    const float* __restrict__ w1, const float* __restrict__ b1,
    const float* __restrict__ w2, const float* __restrict__ b2,
    const float* __restrict__ fcw, const float* __restrict__ fcb,
    float* __restrict__ out)
{
    extern __shared__ float sm[];
    float* sm_in = sm + OFF_IN;   // [64][269]  padded embedded input
    float* sm_A  = sm + OFF_A;    // [256][140] padded layer-1 output (post top-k/tanh)
    float* sm_T2 = sm + OFF_T2;   // [1024]     layer-2 output (flatten order c*4+j)
    float* sm_w  = sm + OFF_W;    // [16][88]   per-warp conv2 weight scratch

    const int tid = threadIdx.x, lane = tid & 31, wid = tid >> 5, b = blockIdx.x;
    const float NEG_INF = __int_as_float(0xff800000);

    // ---- Phase 0: zero padded buffers (establishes conv zero-padding) ----
    for (int i = tid; i < ZERO_FLOATS; i += NTHREADS) sm[i] = 0.f;
    __syncthreads();

    // ---- Phase 1: embedding gather, transposed to (D, S), padded by 6 ----
    const int* xb = x + b * S;
    for (int i = tid; i < S * Dm; i += NTHREADS) {
        int s = i >> 6, d = i & 63;
        sm_in[d * STR1 + 6 + s] = emb[(long)xb[s] * Dm + d];
    }
    __syncthreads();

    // ---- Phase 2: conv1 (K=7, groups=64) + fold(pairs) + top-131 + tanh ----
    // Association matches XLA: each conv channel is a complete ascending-k
    // FMA chain; bias added per channel; fold adds the two finished results.
#pragma unroll 1
    for (int ci = wid; ci < 256; ci += NW) {
        int rp = ci >> 3, f = ci & 7;
        int o0 = (2 * rp) * 8 + f, o1 = o0 + 8;
        float wA[7], wB[7];
#pragma unroll
        for (int k = 0; k < 7; k++) { wA[k] = w1[o0 * 7 + k]; wB[k] = w1[o1 * 7 + k]; }
        float bA = b1[o0], bB = b1[o1];
        const float* inA = sm_in + (2 * rp) * STR1;
        const float* inB = inA + STR1;

        int t0 = lane * 9;                          // blocked: preserves index order
        float a[15], bb[15];
#pragma unroll
        for (int i = 0; i < 15; i++) {
            int idx = t0 + i; bool ok = idx < 268;
            a[i]  = ok ? inA[idx] : 0.f;
            bb[i] = ok ? inB[idx] : 0.f;
        }
        float v[9];
#pragma unroll
        for (int j = 0; j < 9; j++) {
            float sA = 0.f, sB = 0.f;
#pragma unroll
            for (int k = 0; k < 7; k++) {           // two independent ascending chains
                sA = fmaf(wA[k], a[j + k], sA);
                sB = fmaf(wB[k], bb[j + k], sB);
            }
            float acc = (sA + bA) + (sB + bB);      // fold after completed channels
            v[j] = (t0 + j < L1_LEN) ? acc : NEG_INF;
        }
        topk_write<9>(v, K1, sm_A + ci * STR2 + 4, lane);
    }
    __syncthreads();

    // ---- Phase 3: conv2 (K=5, groups=32, 8 in-ch/group) + fold + top-4 + tanh ----
    float* wbuf = sm_w + wid * 88;
#pragma unroll 1
    for (int ci = wid; ci < 256; ci += NW) {
        int rpp = ci >> 4, f2 = ci & 15;
        int g0 = 2 * rpp, g1 = g0 + 1;
        // Stage 80 weights + 2 biases in per-warp smem
        for (int idx = lane; idx < 80; idx += 32) {
            int g = (idx < 40) ? g0 : g1;
            int loc = (idx < 40) ? idx : idx - 40;
            wbuf[idx] = w2[(g * 16 + f2) * 40 + loc];
        }
        if (lane == 0) { wbuf[80] = b2[g0 * 16 + f2]; wbuf[81] = b2[g1 * 16 + f2]; }
        __syncwarp();

        int t0 = lane * 5;
        float bA = wbuf[80], bB = wbuf[81];
        float accA[5], accB[5];
#pragma unroll
        for (int j = 0; j < 5; j++) { accA[j] = 0.f; accB[j] = 0.f; }
        float win[9];
#pragma unroll
        for (int gi = 0; gi < 2; gi++) {
            int g = gi ? g1 : g0;
            float* acc = gi ? accB : accA;
#pragma unroll
            for (int i = 0; i < 8; i++) {           // (i outer, k inner) ascending chain
                const float* row = sm_A + (g * 8 + i) * STR2;
#pragma unroll
                for (int q = 0; q < 9; q++) {
                    int idx = t0 + q;
                    win[q] = (idx < 139) ? row[idx] : 0.f;
                }
#pragma unroll
                for (int k2 = 0; k2 < 5; k2++) {
                    float w = wbuf[gi * 40 + i * 5 + k2];
#pragma unroll
                    for (int j = 0; j < 5; j++)
                        acc[j] = fmaf(w, win[j + k2], acc[j]);
                }
            }
        }
        float v[5];
#pragma unroll
        for (int j = 0; j < 5; j++) {
            float r = (accA[j] + bA) + (accB[j] + bB);   // fold after completed channels
            v[j] = (t0 + j < L2_LEN) ? r : NEG_INF;
        }
        topk_write<5>(v, K2, sm_T2 + ci * 4, lane);      // flatten order: c2*4 + j
        __syncwarp();
    }
    __syncthreads();

    // ---- Phase 4: FC (1024 -> 6), warp per class ----
    if (wid < 6) {
        float s = 0.f;
        for (int d = lane; d < 1024; d += 32)
            s = fmaf(fcw[wid * 1024 + d], sm_T2[d], s);
#pragma unroll
        for (int o = 16; o; o >>= 1) s += __shfl_xor_sync(FULL, s, o);
        if (lane == 0) out[b * 6 + wid] = s + fcb[wid];
    }
}

extern "C" void kernel_launch(void* const* d_in, const int* in_sizes, int n_in,
                              void* d_out, int out_size) {
    const int*   x   = (const int*)d_in[0];
    const float* emb = (const float*)d_in[1];
    const float* w1  = (const float*)d_in[2];
    const float* b1  = (const float*)d_in[3];
    const float* w2  = (const float*)d_in[4];
    const float* b2  = (const float*)d_in[5];
    const float* fcw = (const float*)d_in[6];
    const float* fcb = (const float*)d_in[7];
    float* out = (float*)d_out;

    cudaFuncSetAttribute(dcnn_kernel, cudaFuncAttributeMaxDynamicSharedMemorySize, SMEM_BYTES);
    dcnn_kernel<<<512, NTHREADS, SMEM_BYTES>>>(x, emb, w1, b1, w2, b2, fcw, fcb, out);
}

// round 7
// speedup vs baseline: 1.6187x; 1.6187x over previous
#include <cuda_runtime.h>
#include <cuda_bf16.h>

#define FULL 0xffffffffu

static constexpr int S = 256, Dm = 64;
static constexpr int STR1 = 269;            // padded emb row: 6 + 256 + 6 (+1 spare)
static constexpr int L1_LEN = 262, K1 = 131;
static constexpr int STR2 = 140;            // padded A row: 4 + 131 + 4 (+1 spare)
static constexpr int L2_LEN = 135, K2 = 4;
static constexpr int NTHREADS = 512;
static constexpr int NW = NTHREADS / 32;    // 16 warps

static constexpr int OFF_IN = 0;                      // 64*269 floats
static constexpr int OFF_A  = 64 * STR1;              // 256*140 floats
static constexpr int OFF_T2 = OFF_A + 256 * STR2;     // 1024 floats
static constexpr int OFF_W  = OFF_T2 + 1024;          // 16*88 floats
static constexpr int SMEM_FLOATS = OFF_W + NW * 88;
static constexpr int SMEM_BYTES  = SMEM_FLOATS * 4;   // ~222 KB (< 227KB opt-in)
static constexpr int ZERO_FLOATS = OFF_T2;            // zero sm_in + sm_A (pads!)

// Monotone float -> uint key (total order, -inf smallest)
__device__ __forceinline__ unsigned fkey(float f) {
    unsigned b = __float_as_uint(f);
    return (b & 0x80000000u) ? ~b : (b | 0x80000000u);
}

__device__ __forceinline__ int iscan(int v, int lane) {
#pragma unroll
    for (int d = 1; d < 32; d <<= 1) {
        int n = __shfl_up_sync(FULL, v, d);
        if (lane >= d) v += n;
    }
    return v;
}

// Warp-collective, order-preserving top-k select of values held blocked across
// lanes (lane l holds NV consecutive positions). Invalid slots must be -inf.
// Writes exactly k values (tanh applied) in original index order. Semantics
// match jax.lax.top_k (lowest-index tie-break) + sorted indices.
//
// Radix bisection processes 2 bits/step with the three candidate counts packed
// into one 32-bit redux (10-bit fields; per-field max 288 < 1024, no carry),
// and exits early as soon as a candidate separates exactly k values (then
// {u >= cand} IS the top-k set -- no ties possible by construction).
template <int NV>
__device__ __forceinline__ void topk_write(const float* v, int k, float* outrow, int lane) {
    unsigned u[NV];
#pragma unroll
    for (int j = 0; j < NV; j++) u[j] = fkey(v[j]);

    unsigned thr = 0;
    bool clean = false;
#pragma unroll 1
    for (int bit = 31; bit >= 1; bit -= 2) {
        unsigned c1 = thr | (1u << (bit - 1));
        unsigned c2 = thr | (2u << (bit - 1));
        unsigned c3 = thr | (3u << (bit - 1));
        unsigned p = 0;
#pragma unroll
        for (int j = 0; j < NV; j++) {
            p += (u[j] >= c1);
            p += (u[j] >= c2) ? 1024u : 0u;
            p += (u[j] >= c3) ? (1024u * 1024u) : 0u;
        }
        p = __reduce_add_sync(FULL, p);
        int n1 = p & 1023, n2 = (p >> 10) & 1023, n3 = p >> 20;
        // counts nonincreasing: n1 >= n2 >= n3. Take largest candidate with count >= k.
        int cc;
        if (n3 >= k)      { thr = c3; cc = n3; }
        else if (n2 >= k) { thr = c2; cc = n2; }
        else if (n1 >= k) { thr = c1; cc = n1; }
        else              { cc = -1; }
        if (cc == k) { clean = true; break; }
    }

    if (clean) {
        // selected set is exactly { u >= thr }, size k, no tie ambiguity
        int kc = 0;
#pragma unroll
        for (int j = 0; j < NV; j++) kc += (u[j] >= thr);
        int pos = iscan(kc, lane) - kc;
#pragma unroll
        for (int j = 0; j < NV; j++)
            if (u[j] >= thr) outrow[pos++] = tanhf(v[j]);
        return;
    }

    // Full-resolution tie path: thr is now the exact k-th largest key.
    int gt = 0, eq = 0;
#pragma unroll
    for (int j = 0; j < NV; j++) { gt += (u[j] > thr); eq += (u[j] == thr); }
    int gt_tot = __reduce_add_sync(FULL, gt);
    int extra = k - gt_tot;                       // ties to keep (earliest-index)
    int eq_excl = iscan(eq, lane) - eq;
    int myq = extra - eq_excl;
    myq = myq < 0 ? 0 : (myq > eq ? eq : myq);
    int kc = gt + myq;
    int pos = iscan(kc, lane) - kc;               // ordered compaction offset
    int used = 0;
#pragma unroll
    for (int j = 0; j < NV; j++) {
        bool keep = (u[j] > thr);
        if (!keep && u[j] == thr && used < myq) { keep = true; used++; }
        if (keep) outrow[pos++] = tanhf(v[j]);
    }
}

__global__ void __launch_bounds__(NTHREADS, 1) dcnn_kernel(
    const int* __restrict__ x, const float* __restrict__ emb,
    const float* __restrict__ w1, const float* __restrict__ b1,
    const float* __restrict__ w2, const float* __restrict__ b2,
    const float* __restrict__ fcw, const float* __restrict__ fcb,
    float* __restrict__ out)
{
    extern __shared__ float sm[];
    float* sm_in = sm + OFF_IN;   // [64][269]  padded embedded input
    float* sm_A  = sm + OFF_A;    // [256][140] padded layer-1 output (post top-k/tanh)
    float* sm_T2 = sm + OFF_T2;   // [1024]     layer-2 output (flatten order c*4+j)
    float* sm_w  = sm + OFF_W;    // [16][88]   per-warp conv2 weight scratch

    const int tid = threadIdx.x, lane = tid & 31, wid = tid >> 5, b = blockIdx.x;
    const float NEG_INF = __int_as_float(0xff800000);

    // ---- Phase 0: zero padded buffers (establishes conv zero-padding) ----
    for (int i = tid; i < ZERO_FLOATS; i += NTHREADS) sm[i] = 0.f;
    __syncthreads();

    // ---- Phase 1: embedding gather, transposed to (D, S), padded by 6 ----
    const int* xb = x + b * S;
    for (int i = tid; i < S * Dm; i += NTHREADS) {
        int s = i >> 6, d = i & 63;
        sm_in[d * STR1 + 6 + s] = emb[(long)xb[s] * Dm + d];
    }
    __syncthreads();

    // ---- Phase 2: conv1 (K=7, groups=64) + fold(pairs) + top-131 + tanh ----
    // Association matches XLA: each conv channel is a complete ascending-k
    // FMA chain; bias added per channel; fold adds the two finished results.
#pragma unroll 1
    for (int ci = wid; ci < 256; ci += NW) {
        int rp = ci >> 3, f = ci & 7;
        int o0 = (2 * rp) * 8 + f, o1 = o0 + 8;
        float wA[7], wB[7];
#pragma unroll
        for (int k = 0; k < 7; k++) { wA[k] = w1[o0 * 7 + k]; wB[k] = w1[o1 * 7 + k]; }
        float bA = b1[o0], bB = b1[o1];
        const float* inA = sm_in + (2 * rp) * STR1;
        const float* inB = inA + STR1;

        int t0 = lane * 9;                          // blocked: preserves index order
        float a[15], bb[15];
#pragma unroll
        for (int i = 0; i < 15; i++) {
            int idx = t0 + i; bool ok = idx < 268;
            a[i]  = ok ? inA[idx] : 0.f;
            bb[i] = ok ? inB[idx] : 0.f;
        }
        float v[9];
#pragma unroll
        for (int j = 0; j < 9; j++) {
            float sA = 0.f, sB = 0.f;
#pragma unroll
            for (int k = 0; k < 7; k++) {           // two independent ascending chains
                sA = fmaf(wA[k], a[j + k], sA);
                sB = fmaf(wB[k], bb[j + k], sB);
            }
            float acc = (sA + bA) + (sB + bB);      // fold after completed channels
            v[j] = (t0 + j < L1_LEN) ? acc : NEG_INF;
        }
        topk_write<9>(v, K1, sm_A + ci * STR2 + 4, lane);
    }
    __syncthreads();

    // ---- Phase 3: conv2 (K=5, groups=32, 8 in-ch/group) + fold + top-4 + tanh ----
    float* wbuf = sm_w + wid * 88;
#pragma unroll 1
    for (int ci = wid; ci < 256; ci += NW) {
        int rpp = ci >> 4, f2 = ci & 15;
        int g0 = 2 * rpp, g1 = g0 + 1;
        // Stage 80 weights + 2 biases in per-warp smem
        for (int idx = lane; idx < 80; idx += 32) {
            int g = (idx < 40) ? g0 : g1;
            int loc = (idx < 40) ? idx : idx - 40;
            wbuf[idx] = w2[(g * 16 + f2) * 40 + loc];
        }
        if (lane == 0) { wbuf[80] = b2[g0 * 16 + f2]; wbuf[81] = b2[g1 * 16 + f2]; }
        __syncwarp();

        int t0 = lane * 5;
        float bA = wbuf[80], bB = wbuf[81];
        float accA[5], accB[5];
#pragma unroll
        for (int j = 0; j < 5; j++) { accA[j] = 0.f; accB[j] = 0.f; }
        float win[9];
#pragma unroll
        for (int gi = 0; gi < 2; gi++) {
            int g = gi ? g1 : g0;
            float* acc = gi ? accB : accA;
#pragma unroll
            for (int i = 0; i < 8; i++) {           // (i outer, k inner) ascending chain
                const float* row = sm_A + (g * 8 + i) * STR2;
#pragma unroll
                for (int q = 0; q < 9; q++) {
                    int idx = t0 + q;
                    win[q] = (idx < 139) ? row[idx] : 0.f;
                }
#pragma unroll
                for (int k2 = 0; k2 < 5; k2++) {
                    float w = wbuf[gi * 40 + i * 5 + k2];
#pragma unroll
                    for (int j = 0; j < 5; j++)
                        acc[j] = fmaf(w, win[j + k2], acc[j]);
                }
            }
        }
        float v[5];
#pragma unroll
        for (int j = 0; j < 5; j++) {
            float r = (accA[j] + bA) + (accB[j] + bB);   // fold after completed channels
            v[j] = (t0 + j < L2_LEN) ? r : NEG_INF;
        }
        topk_write<5>(v, K2, sm_T2 + ci * 4, lane);      // flatten order: c2*4 + j
        __syncwarp();
    }
    __syncthreads();

    // ---- Phase 4: FC (1024 -> 6), warp per class ----
    if (wid < 6) {
        float s = 0.f;
        for (int d = lane; d < 1024; d += 32)
            s = fmaf(fcw[wid * 1024 + d], sm_T2[d], s);
#pragma unroll
        for (int o = 16; o; o >>= 1) s += __shfl_xor_sync(FULL, s, o);
        if (lane == 0) out[b * 6 + wid] = s + fcb[wid];
    }
}

extern "C" void kernel_launch(void* const* d_in, const int* in_sizes, int n_in,
                              void* d_out, int out_size) {
    const int*   x   = (const int*)d_in[0];
    const float* emb = (const float*)d_in[1];
    const float* w1  = (const float*)d_in[2];
    const float* b1  = (const float*)d_in[3];
    const float* w2  = (const float*)d_in[4];
    const float* b2  = (const float*)d_in[5];
    const float* fcw = (const float*)d_in[6];
    const float* fcb = (const float*)d_in[7];
    float* out = (float*)d_out;

    cudaFuncSetAttribute(dcnn_kernel, cudaFuncAttributeMaxDynamicSharedMemorySize, SMEM_BYTES);
    dcnn_kernel<<<512, NTHREADS, SMEM_BYTES>>>(x, emb, w1, b1, w2, b2, fcw, fcb, out);
}

// round 8
// speedup vs baseline: 1.7060x; 1.0539x over previous
#include <cuda_runtime.h>
#include <cuda_bf16.h>

#define FULL 0xffffffffu

static constexpr int S = 256, Dm = 64;
static constexpr int STR1 = 269;            // padded emb row: 6 + 256 + 6 (+1 spare)
static constexpr int L1_LEN = 262, K1 = 131;
static constexpr int STR2 = 140;            // padded A row: 4 + 131 + 4 (+1 spare)
static constexpr int L2_LEN = 135, K2 = 4;
static constexpr int NTHREADS = 1024;       // 32 warps -> RF forces <=64 regs, occ 50%
static constexpr int NW = NTHREADS / 32;    // 32 warps

static constexpr int OFF_IN = 0;                      // 64*269 floats
static constexpr int OFF_A  = 64 * STR1;              // 256*140 floats
static constexpr int OFF_T2 = OFF_A + 256 * STR2;     // 1024 floats
static constexpr int OFF_W  = OFF_T2 + 1024;          // 32*88 floats
static constexpr int SMEM_FLOATS = OFF_W + NW * 88;
static constexpr int SMEM_BYTES  = SMEM_FLOATS * 4;   // ~227.6 KB (< 232KB opt-in)
static constexpr int ZERO_FLOATS = OFF_T2;            // zero sm_in + sm_A (pads!)

// Monotone float -> uint key (total order, -inf smallest)
__device__ __forceinline__ unsigned fkey(float f) {
    unsigned b = __float_as_uint(f);
    return (b & 0x80000000u) ? ~b : (b | 0x80000000u);
}

__device__ __forceinline__ int iscan(int v, int lane) {
#pragma unroll
    for (int d = 1; d < 32; d <<= 1) {
        int n = __shfl_up_sync(FULL, v, d);
        if (lane >= d) v += n;
    }
    return v;
}

// Warp-collective, order-preserving top-k select of values held blocked across
// lanes (lane l holds NV consecutive positions). Invalid slots must be -inf.
// Writes exactly k values (tanh applied) in original index order. Semantics
// match jax.lax.top_k (lowest-index tie-break) + sorted indices.
//
// Radix bisection: 2 bits/step, three candidate counts packed into one 32-bit
// redux (10-bit fields; per-field max 288 < 1024, no carry). Early exit when a
// candidate separates exactly k values ({u >= cand} IS the top-k set).
template <int NV>
__device__ __forceinline__ void topk_write(const float* v, int k, float* outrow, int lane) {
    unsigned u[NV];
#pragma unroll
    for (int j = 0; j < NV; j++) u[j] = fkey(v[j]);

    unsigned thr = 0;
    bool clean = false;
#pragma unroll 1
    for (int bit = 31; bit >= 1; bit -= 2) {
        unsigned c1 = thr | (1u << (bit - 1));
        unsigned c2 = thr | (2u << (bit - 1));
        unsigned c3 = thr | (3u << (bit - 1));
        unsigned p = 0;
#pragma unroll
        for (int j = 0; j < NV; j++) {
            p += (u[j] >= c1);
            p += (u[j] >= c2) ? 1024u : 0u;
            p += (u[j] >= c3) ? (1024u * 1024u) : 0u;
        }
        p = __reduce_add_sync(FULL, p);
        int n1 = p & 1023, n2 = (p >> 10) & 1023, n3 = p >> 20;
        int cc;
        if (n3 >= k)      { thr = c3; cc = n3; }
        else if (n2 >= k) { thr = c2; cc = n2; }
        else if (n1 >= k) { thr = c1; cc = n1; }
        else              { cc = -1; }
        if (cc == k) { clean = true; break; }
    }

    if (clean) {
        int kc = 0;
#pragma unroll
        for (int j = 0; j < NV; j++) kc += (u[j] >= thr);
        int pos = iscan(kc, lane) - kc;
#pragma unroll
        for (int j = 0; j < NV; j++)
            if (u[j] >= thr) outrow[pos++] = tanhf(v[j]);
        return;
    }

    // Full-resolution tie path: thr is the exact k-th largest key.
    int gt = 0, eq = 0;
#pragma unroll
    for (int j = 0; j < NV; j++) { gt += (u[j] > thr); eq += (u[j] == thr); }
    int gt_tot = __reduce_add_sync(FULL, gt);
    int extra = k - gt_tot;
    int eq_excl = iscan(eq, lane) - eq;
    int myq = extra - eq_excl;
    myq = myq < 0 ? 0 : (myq > eq ? eq : myq);
    int kc = gt + myq;
    int pos = iscan(kc, lane) - kc;
    int used = 0;
#pragma unroll
    for (int j = 0; j < NV; j++) {
        bool keep = (u[j] > thr);
        if (!keep && u[j] == thr && used < myq) { keep = true; used++; }
        if (keep) outrow[pos++] = tanhf(v[j]);
    }
}

__global__ void __launch_bounds__(NTHREADS, 1) dcnn_kernel(
    const int* __restrict__ x, const float* __restrict__ emb,
    const float* __restrict__ w1, const float* __restrict__ b1,
    const float* __restrict__ w2, const float* __restrict__ b2,
    const float* __restrict__ fcw, const float* __restrict__ fcb,
    float* __restrict__ out)
{
    extern __shared__ float sm[];
    float* sm_in = sm + OFF_IN;   // [64][269]  padded embedded input
    float* sm_A  = sm + OFF_A;    // [256][140] padded layer-1 output (post top-k/tanh)
    float* sm_T2 = sm + OFF_T2;   // [1024]     layer-2 output (flatten order c*4+j)
    float* sm_w  = sm + OFF_W;    // [32][88]   per-warp conv2 weight scratch

    const int tid = threadIdx.x, lane = tid & 31, wid = tid >> 5, b = blockIdx.x;
    const float NEG_INF = __int_as_float(0xff800000);

    // ---- Phase 0: zero padded buffers (establishes conv zero-padding) ----
    for (int i = tid; i < ZERO_FLOATS; i += NTHREADS) sm[i] = 0.f;
    __syncthreads();

    // ---- Phase 1: embedding gather, transposed to (D, S), padded by 6 ----
    const int* xb = x + b * S;
    for (int i = tid; i < S * Dm; i += NTHREADS) {
        int s = i >> 6, d = i & 63;
        sm_in[d * STR1 + 6 + s] = emb[(long)xb[s] * Dm + d];
    }
    __syncthreads();

    // ---- Phase 2: conv1 (K=7, groups=64) + fold(pairs) + top-131 + tanh ----
    // Association matches XLA: each conv channel is a complete ascending-k
    // FMA chain; bias added per channel; fold adds the two finished results.
#pragma unroll 1
    for (int ci = wid; ci < 256; ci += NW) {
        int rp = ci >> 3, f = ci & 7;
        int o0 = (2 * rp) * 8 + f, o1 = o0 + 8;
        float wA[7], wB[7];
#pragma unroll
        for (int k = 0; k < 7; k++) { wA[k] = w1[o0 * 7 + k]; wB[k] = w1[o1 * 7 + k]; }
        float bA = b1[o0], bB = b1[o1];
        const float* inA = sm_in + (2 * rp) * STR1;
        const float* inB = inA + STR1;

        int t0 = lane * 9;                          // blocked: preserves index order
        float a[15], bb[15];
#pragma unroll
        for (int i = 0; i < 15; i++) {
            int idx = t0 + i; bool ok = idx < 268;
            a[i]  = ok ? inA[idx] : 0.f;
            bb[i] = ok ? inB[idx] : 0.f;
        }
        float v[9];
#pragma unroll
        for (int j = 0; j < 9; j++) {
            float sA = 0.f, sB = 0.f;
#pragma unroll
            for (int k = 0; k < 7; k++) {           // two independent ascending chains
                sA = fmaf(wA[k], a[j + k], sA);
                sB = fmaf(wB[k], bb[j + k], sB);
            }
            float acc = (sA + bA) + (sB + bB);      // fold after completed channels
            v[j] = (t0 + j < L1_LEN) ? acc : NEG_INF;
        }
        topk_write<9>(v, K1, sm_A + ci * STR2 + 4, lane);
    }
    __syncthreads();

    // ---- Phase 3: conv2 (K=5, groups=32, 8 in-ch/group) + fold + top-4 + tanh ----
    float* wbuf = sm_w + wid * 88;
#pragma unroll 1
    for (int ci = wid; ci < 256; ci += NW) {
        int rpp = ci >> 4, f2 = ci & 15;
        int g0 = 2 * rpp, g1 = g0 + 1;
        // Stage 80 weights + 2 biases in per-warp smem
        for (int idx = lane; idx < 80; idx += 32) {
            int g = (idx < 40) ? g0 : g1;
            int loc = (idx < 40) ? idx : idx - 40;
            wbuf[idx] = w2[(g * 16 + f2) * 40 + loc];
        }
        if (lane == 0) { wbuf[80] = b2[g0 * 16 + f2]; wbuf[81] = b2[g1 * 16 + f2]; }
        __syncwarp();

        int t0 = lane * 5;
        float bA = wbuf[80], bB = wbuf[81];
        float accA[5], accB[5];
#pragma unroll
        for (int j = 0; j < 5; j++) { accA[j] = 0.f; accB[j] = 0.f; }
        float win[9];
#pragma unroll
        for (int gi = 0; gi < 2; gi++) {
            int g = gi ? g1 : g0;
            float* acc = gi ? accB : accA;
#pragma unroll
            for (int i = 0; i < 8; i++) {           // (i outer, k inner) ascending chain
                const float* row = sm_A + (g * 8 + i) * STR2;
#pragma unroll
                for (int q = 0; q < 9; q++) {
                    int idx = t0 + q;
                    win[q] = (idx < 139) ? row[idx] : 0.f;
                }
#pragma unroll
                for (int k2 = 0; k2 < 5; k2++) {
                    float w = wbuf[gi * 40 + i * 5 + k2];
#pragma unroll
                    for (int j = 0; j < 5; j++)
                        acc[j] = fmaf(w, win[j + k2], acc[j]);
                }
            }
        }
        float v[5];
#pragma unroll
        for (int j = 0; j < 5; j++) {
            float r = (accA[j] + bA) + (accB[j] + bB);   // fold after completed channels
            v[j] = (t0 + j < L2_LEN) ? r : NEG_INF;
        }
        topk_write<5>(v, K2, sm_T2 + ci * 4, lane);      // flatten order: c2*4 + j
        __syncwarp();
    }
    __syncthreads();

    // ---- Phase 4: FC (1024 -> 6), warp per class ----
    if (wid < 6) {
        float s = 0.f;
        for (int d = lane; d < 1024; d += 32)
            s = fmaf(fcw[wid * 1024 + d], sm_T2[d], s);
#pragma unroll
        for (int o = 16; o; o >>= 1) s += __shfl_xor_sync(FULL, s, o);
        if (lane == 0) out[b * 6 + wid] = s + fcb[wid];
    }
}

extern "C" void kernel_launch(void* const* d_in, const int* in_sizes, int n_in,
                              void* d_out, int out_size) {
    const int*   x   = (const int*)d_in[0];
    const float* emb = (const float*)d_in[1];
    const float* w1  = (const float*)d_in[2];
    const float* b1  = (const float*)d_in[3];
    const float* w2  = (const float*)d_in[4];
    const float* b2  = (const float*)d_in[5];
    const float* fcw = (const float*)d_in[6];
    const float* fcb = (const float*)d_in[7];
    float* out = (float*)d_out;

    cudaFuncSetAttribute(dcnn_kernel, cudaFuncAttributeMaxDynamicSharedMemorySize, SMEM_BYTES);
    dcnn_kernel<<<512, NTHREADS, SMEM_BYTES>>>(x, emb, w1, b1, w2, b2, fcw, fcb, out);
}

// round 9
// speedup vs baseline: 1.9473x; 1.1414x over previous
#include <cuda_runtime.h>

#define FULL 0xffffffffu

static constexpr int S = 256, Dm = 64;
static constexpr int STR1 = 269;            // padded emb row: 6 + 256 + 6 (+1 spare)
static constexpr int L1_LEN = 262, K1 = 131;
static constexpr int STR2 = 140;            // padded A row: 4 + 131 + 4 (+1 spare)
static constexpr int NTHREADS = 1024;       // 32 warps
static constexpr int NW = NTHREADS / 32;

static constexpr int OFF_IN = 0;                      // 64*269 floats
static constexpr int OFF_A  = 64 * STR1;              // 256*140 floats
static constexpr int OFF_T2 = OFF_A + 256 * STR2;     // 1024 floats
static constexpr int SMEM_FLOATS = OFF_T2 + 1024;
static constexpr int SMEM_BYTES  = SMEM_FLOATS * 4;   // ~216.3 KB
static constexpr int ZERO_FLOATS = OFF_T2;            // zero sm_in + sm_A (pads!)

// Monotone float -> uint key (total order). Inverse restores the exact float.
__device__ __forceinline__ unsigned fkey(float f) {
    unsigned b = __float_as_uint(f);
    return (b & 0x80000000u) ? ~b : (b | 0x80000000u);
}
__device__ __forceinline__ float funkey(unsigned u) {
    unsigned b = (u & 0x80000000u) ? (u & 0x7fffffffu) : ~u;
    return __uint_as_float(b);
}

// Fast tanh: abs error ~1e-6 (applied only AFTER selection -> no selection impact)
__device__ __forceinline__ float tanh_fast(float x) {
    float ax = fabsf(x);
    float t = __expf(-2.f * ax);
    float r = __fdividef(1.f - t, 1.f + t);
    return copysignf(r, x);
}

__device__ __forceinline__ int iscan(int v, int lane) {
#pragma unroll
    for (int d = 1; d < 32; d <<= 1) {
        int n = __shfl_up_sync(FULL, v, d);
        if (lane >= d) v += n;
    }
    return v;
}

__device__ __forceinline__ unsigned long long umax64(unsigned long long a, unsigned long long b) { return a > b ? a : b; }
__device__ __forceinline__ unsigned long long umin64(unsigned long long a, unsigned long long b) { return a < b ? a : b; }

// Warp-collective order-preserving top-k on keys u[] (blocked across lanes,
// invalid slots key 0 = below every real key). Writes k tanh'd values in
// original index order; jax.lax.top_k tie semantics (earliest index).
// 2-bit radix bisection, packed counts, early exit on exact separation.
template <int NV>
__device__ __forceinline__ void topk_write_keys(const unsigned* u, int k, float* outrow, int lane) {
    unsigned thr = 0;
    bool clean = false;
#pragma unroll 1
    for (int bit = 31; bit >= 1; bit -= 2) {
        unsigned c1 = thr | (1u << (bit - 1));
        unsigned c2 = thr | (2u << (bit - 1));
        unsigned c3 = thr | (3u << (bit - 1));
        unsigned p = 0;
#pragma unroll
        for (int j = 0; j < NV; j++) {
            p += (u[j] >= c1);
            p += (u[j] >= c2) ? 1024u : 0u;
            p += (u[j] >= c3) ? (1024u * 1024u) : 0u;
        }
        p = __reduce_add_sync(FULL, p);
        int n1 = p & 1023, n2 = (p >> 10) & 1023, n3 = p >> 20;
        int cc;
        if (n3 >= k)      { thr = c3; cc = n3; }
        else if (n2 >= k) { thr = c2; cc = n2; }
        else if (n1 >= k) { thr = c1; cc = n1; }
        else              { cc = -1; }
        if (cc == k) { clean = true; break; }
    }

    if (clean) {
        int kc = 0;
#pragma unroll
        for (int j = 0; j < NV; j++) kc += (u[j] >= thr);
        int pos = iscan(kc, lane) - kc;
#pragma unroll
        for (int j = 0; j < NV; j++)
            if (u[j] >= thr) outrow[pos++] = tanh_fast(funkey(u[j]));
        return;
    }

    // Full-resolution tie path: thr is the exact k-th largest key.
    int gt = 0, eq = 0;
#pragma unroll
    for (int j = 0; j < NV; j++) { gt += (u[j] > thr); eq += (u[j] == thr); }
    int gt_tot = __reduce_add_sync(FULL, gt);
    int extra = k - gt_tot;
    int eq_excl = iscan(eq, lane) - eq;
    int myq = extra - eq_excl;
    myq = myq < 0 ? 0 : (myq > eq ? eq : myq);
    int kc = gt + myq;
    int pos = iscan(kc, lane) - kc;
    int used = 0;
#pragma unroll
    for (int j = 0; j < NV; j++) {
        bool keep = (u[j] > thr);
        if (!keep && u[j] == thr && used < myq) { keep = true; used++; }
        if (keep) outrow[pos++] = tanh_fast(funkey(u[j]));
    }
}

__global__ void __launch_bounds__(NTHREADS, 1) dcnn_kernel(
    const int* __restrict__ x, const float* __restrict__ emb,
    const float* __restrict__ w1, const float* __restrict__ b1,
    const float* __restrict__ w2, const float* __restrict__ b2,
    const float* __restrict__ fcw, const float* __restrict__ fcb,
    float* __restrict__ out)
{
    extern __shared__ float sm[];
    float* sm_in = sm + OFF_IN;   // [64][269]  padded embedded input
    float* sm_A  = sm + OFF_A;    // [256][140] padded layer-1 output (post top-k/tanh)
    float* sm_T2 = sm + OFF_T2;   // [1024]     layer-2 output (flatten order c*4+j)

    const int tid = threadIdx.x, lane = tid & 31, wid = tid >> 5, b = blockIdx.x;

    // ---- Phase 0: zero padded buffers (establishes conv zero-padding) ----
    for (int i = tid; i < ZERO_FLOATS; i += NTHREADS) sm[i] = 0.f;
    __syncthreads();

    // ---- Phase 1: embedding gather, transposed to (D, S), padded by 6 ----
    const int* xb = x + b * S;
    for (int i = tid; i < S * Dm; i += NTHREADS) {
        int s = i >> 6, d = i & 63;
        sm_in[d * STR1 + 6 + s] = emb[(long)xb[s] * Dm + d];
    }
    __syncthreads();

    // ---- Phase 2: conv1 (K=7, groups=64) + fold(pairs) + top-131 + tanh ----
    // Association matches XLA: each conv channel is a complete ascending-k
    // FMA chain; bias added per channel; fold adds the two finished results.
#pragma unroll 1
    for (int ci = wid; ci < 256; ci += NW) {
        int rp = ci >> 3, f = ci & 7;
        int o0 = (2 * rp) * 8 + f, o1 = o0 + 8;
        float wA[7], wB[7];
#pragma unroll
        for (int k = 0; k < 7; k++) { wA[k] = w1[o0 * 7 + k]; wB[k] = w1[o1 * 7 + k]; }
        float bA = b1[o0], bB = b1[o1];
        const float* inA = sm_in + (2 * rp) * STR1;
        const float* inB = inA + STR1;

        int t0 = lane * 9;                          // blocked: preserves index order
        float a[15], bb[15];
#pragma unroll
        for (int i = 0; i < 15; i++) {
            int idx = t0 + i; bool ok = idx < 268;
            a[i]  = ok ? inA[idx] : 0.f;
            bb[i] = ok ? inB[idx] : 0.f;
        }
        unsigned u[9];
#pragma unroll
        for (int j = 0; j < 9; j++) {
            float sA = 0.f, sB = 0.f;
#pragma unroll
            for (int k = 0; k < 7; k++) {           // two independent ascending chains
                sA = fmaf(wA[k], a[j + k], sA);
                sB = fmaf(wB[k], bb[j + k], sB);
            }
            float acc = (sA + bA) + (sB + bB);      // fold after completed channels
            u[j] = (t0 + j < L1_LEN) ? fkey(acc) : 0u;   // 0 = below all real keys
        }
        topk_write_keys<9>(u, K1, sm_A + ci * STR2 + 4, lane);
    }
    __syncthreads();

    // ---- Phase 3: conv2 (K=5, groups=32) + fold + top-4 + tanh ----
    // Thread-per-(channel, position-chunk): 256 channels x 4 chunks of ~34.
    // Thread-local sorted top-4 of packed (key<<32 | ~index); chunk results
    // merged with a shuffle bitonic half-cleaner (all u64 distinct by index,
    // so (value, earliest-index) ordering is exact).
    {
        const int rpp   = wid >> 1;                 // 0..15
        const int half  = wid & 1;
        const int f2    = half * 8 + (lane >> 2);   // 0..15
        const int chunk = lane & 3;
        const int ci    = rpp * 16 + f2;
        const int g0    = 2 * rpp;
        const int o0    = g0 * 16 + f2, o1 = o0 + 16;
        const float bA  = b2[o0], bB = b2[o1];
        const float* W0 = w2 + o0 * 40;
        const float* W1 = w2 + o1 * 40;
        const float* rows0 = sm_A + (g0 * 8) * STR2;
        const float* rows1 = rows0 + 8 * STR2;

        const int p0 = chunk * 34;
        const int np = (chunk == 3) ? 33 : 34;      // position count in this chunk

        unsigned long long m0 = 0, m1 = 0, m2 = 0, m3 = 0;

#pragma unroll 1
        for (int pb = 0; pb < 34; pb += 7) {
            const int base = p0 + pb;
            const int nn = min(7, np - pb);
            float accA[7] = {0, 0, 0, 0, 0, 0, 0};
            float accB[7] = {0, 0, 0, 0, 0, 0, 0};
            float win[11];
#pragma unroll
            for (int i = 0; i < 8; i++) {           // channel A: (i asc, k2 asc) chain
                const float* row = rows0 + i * STR2;
#pragma unroll
                for (int q = 0; q < 10; q++) win[q] = row[base + q];
                win[10] = (base + 10 < STR2) ? row[base + 10] : 0.f;
#pragma unroll
                for (int k2 = 0; k2 < 5; k2++) {
                    float w = W0[i * 5 + k2];
#pragma unroll
                    for (int j = 0; j < 7; j++)
                        accA[j] = fmaf(w, win[j + k2], accA[j]);
                }
            }
#pragma unroll
            for (int i = 0; i < 8; i++) {           // channel B
                const float* row = rows1 + i * STR2;
#pragma unroll
                for (int q = 0; q < 10; q++) win[q] = row[base + q];
                win[10] = (base + 10 < STR2) ? row[base + 10] : 0.f;
#pragma unroll
                for (int k2 = 0; k2 < 5; k2++) {
                    float w = W1[i * 5 + k2];
#pragma unroll
                    for (int j = 0; j < 7; j++)
                        accB[j] = fmaf(w, win[j + k2], accB[j]);
                }
            }
#pragma unroll
            for (int j = 0; j < 7; j++) {
                if (j < nn) {
                    float r = (accA[j] + bA) + (accB[j] + bB);  // fold after channels
                    int p = base + j;
                    unsigned long long cand =
                        ((unsigned long long)fkey(r) << 32) | (unsigned)(~(unsigned)p);
                    if (cand > m3) {                 // sorted insert (desc)
                        m3 = cand;
                        if (m3 > m2) { unsigned long long t = m2; m2 = m3; m3 = t;
                            if (m2 > m1) { t = m1; m1 = m2; m2 = t;
                                if (m1 > m0) { t = m0; m0 = m1; m1 = t; } } }
                    }
                }
            }
        }

        // Merge the 4 chunk top-4 lists (desc sorted) -> channel top-4
#pragma unroll
        for (int d = 1; d <= 2; d <<= 1) {
            unsigned long long b0 = __shfl_xor_sync(FULL, m0, d);
            unsigned long long b1v = __shfl_xor_sync(FULL, m1, d);
            unsigned long long b2v = __shfl_xor_sync(FULL, m2, d);
            unsigned long long b3v = __shfl_xor_sync(FULL, m3, d);
            // bitonic half-cleaner against reversed partner -> top-4 multiset
            unsigned long long t0v = umax64(m0, b3v);
            unsigned long long t1v = umax64(m1, b2v);
            unsigned long long t2v = umax64(m2, b1v);
            unsigned long long t3v = umax64(m3, b0);
            // clean bitonic 4 -> descending
            unsigned long long s0 = umax64(t0v, t2v), s2 = umin64(t0v, t2v);
            unsigned long long s1 = umax64(t1v, t3v), s3 = umin64(t1v, t3v);
            m0 = umax64(s0, s1); m1 = umin64(s0, s1);
            m2 = umax64(s2, s3); m3 = umin64(s2, s3);
        }

        // Sort the 4 winners by original index (low32 = ~p, so desc-by-low32
        // == ascending p). Full 5-CE network keyed on low 32 bits.
        {
            unsigned long long a0 = m0, a1 = m1, a2 = m2, a3 = m3, t;
            if ((unsigned)a0 < (unsigned)a1) { t = a0; a0 = a1; a1 = t; }
            if ((unsigned)a2 < (unsigned)a3) { t = a2; a2 = a3; a3 = t; }
            if ((unsigned)a0 < (unsigned)a2) { t = a0; a0 = a2; a2 = t; }
            if ((unsigned)a1 < (unsigned)a3) { t = a1; a1 = a3; a3 = t; }
            if ((unsigned)a1 < (unsigned)a2) { t = a1; a1 = a2; a2 = t; }
            unsigned long long sel = (chunk == 0) ? a0 : (chunk == 1) ? a1
                                   : (chunk == 2) ? a2 : a3;
            sm_T2[ci * 4 + chunk] = tanh_fast(funkey((unsigned)(sel >> 32)));
        }
    }
    __syncthreads();

    // ---- Phase 4: FC (1024 -> 6), warp per class ----
    if (wid < 6) {
        float s = 0.f;
        for (int d = lane; d < 1024; d += 32)
            s = fmaf(fcw[wid * 1024 + d], sm_T2[d], s);
#pragma unroll
        for (int o = 16; o; o >>= 1) s += __shfl_xor_sync(FULL, s, o);
        if (lane == 0) out[b * 6 + wid] = s + fcb[wid];
    }
}

extern "C" void kernel_launch(void* const* d_in, const int* in_sizes, int n_in,
                              void* d_out, int out_size) {
    const int*   x   = (const int*)d_in[0];
    const float* emb = (const float*)d_in[1];
    const float* w1  = (const float*)d_in[2];
    const float* b1  = (const float*)d_in[3];
    const float* w2  = (const float*)d_in[4];
    const float* b2  = (const float*)d_in[5];
    const float* fcw = (const float*)d_in[6];
    const float* fcb = (const float*)d_in[7];
    float* out = (float*)d_out;

    cudaFuncSetAttribute(dcnn_kernel, cudaFuncAttributeMaxDynamicSharedMemorySize, SMEM_BYTES);
    dcnn_kernel<<<512, NTHREADS, SMEM_BYTES>>>(x, emb, w1, b1, w2, b2, fcw, fcb, out);
}

// round 10
// speedup vs baseline: 2.4555x; 1.2610x over previous
#include <cuda_runtime.h>

#define FULL 0xffffffffu

static constexpr int S = 256;
static constexpr int STR1 = 269;            // padded emb row: 6 + 256 + 6 (+1 spare)
static constexpr int L1_LEN = 262, K1 = 131;
static constexpr int STR2 = 140;            // padded A row: 4 + 131 + 4 (+1 spare)
static constexpr int NTHREADS = 256;        // 8 warps per CTA (4 slices)
static constexpr int NSLICE = 4;            // rpp slices per CTA
static constexpr int NCTA_PER_B = 4;        // 16 rpp / 4

static constexpr int ROWS_IN = 16;          // emb rows per CTA
static constexpr int ROWS_A  = 64;          // A rows per CTA
static constexpr int OFF_IN = 0;                        // 16*269 = 4304 floats
static constexpr int OFF_A  = ROWS_IN * STR1;           // 64*140 = 8960 floats
static constexpr int SMEM_FLOATS = OFF_A + ROWS_A * STR2;   // 13264
static constexpr int SMEM_BYTES  = SMEM_FLOATS * 4;         // 53056 B -> 4 CTAs/SM

__device__ float g_T2[512 * 1024];          // cross-kernel feature scratch

// Monotone float -> uint key (total order). Inverse restores the exact float.
__device__ __forceinline__ unsigned fkey(float f) {
    unsigned b = __float_as_uint(f);
    return (b & 0x80000000u) ? ~b : (b | 0x80000000u);
}
__device__ __forceinline__ float funkey(unsigned u) {
    unsigned b = (u & 0x80000000u) ? (u & 0x7fffffffu) : ~u;
    return __uint_as_float(b);
}

// Fast tanh: abs error ~1e-6 (applied only AFTER selection -> no selection impact)
__device__ __forceinline__ float tanh_fast(float x) {
    float ax = fabsf(x);
    float t = __expf(-2.f * ax);
    float r = __fdividef(1.f - t, 1.f + t);
    return copysignf(r, x);
}

__device__ __forceinline__ int iscan(int v, int lane) {
#pragma unroll
    for (int d = 1; d < 32; d <<= 1) {
        int n = __shfl_up_sync(FULL, v, d);
        if (lane >= d) v += n;
    }
    return v;
}

__device__ __forceinline__ unsigned long long umax64(unsigned long long a, unsigned long long b) { return a > b ? a : b; }
__device__ __forceinline__ unsigned long long umin64(unsigned long long a, unsigned long long b) { return a < b ? a : b; }

// Warp-collective order-preserving top-k on keys u[] (blocked across lanes,
// invalid slots key 0). Writes k tanh'd values in original index order;
// jax.lax.top_k tie semantics (earliest index). 2-bit radix bisection with
// packed counts and early exit on exact separation.
template <int NV>
__device__ __forceinline__ void topk_write_keys(const unsigned* u, int k, float* outrow, int lane) {
    unsigned thr = 0;
    bool clean = false;
#pragma unroll 1
    for (int bit = 31; bit >= 1; bit -= 2) {
        unsigned c1 = thr | (1u << (bit - 1));
        unsigned c2 = thr | (2u << (bit - 1));
        unsigned c3 = thr | (3u << (bit - 1));
        unsigned p = 0;
#pragma unroll
        for (int j = 0; j < NV; j++) {
            p += (u[j] >= c1);
            p += (u[j] >= c2) ? 1024u : 0u;
            p += (u[j] >= c3) ? (1024u * 1024u) : 0u;
        }
        p = __reduce_add_sync(FULL, p);
        int n1 = p & 1023, n2 = (p >> 10) & 1023, n3 = p >> 20;
        int cc;
        if (n3 >= k)      { thr = c3; cc = n3; }
        else if (n2 >= k) { thr = c2; cc = n2; }
        else if (n1 >= k) { thr = c1; cc = n1; }
        else              { cc = -1; }
        if (cc == k) { clean = true; break; }
    }

    if (clean) {
        int kc = 0;
#pragma unroll
        for (int j = 0; j < NV; j++) kc += (u[j] >= thr);
        int pos = iscan(kc, lane) - kc;
#pragma unroll
        for (int j = 0; j < NV; j++)
            if (u[j] >= thr) outrow[pos++] = tanh_fast(funkey(u[j]));
        return;
    }

    // Full-resolution tie path: thr is the exact k-th largest key.
    int gt = 0, eq = 0;
#pragma unroll
    for (int j = 0; j < NV; j++) { gt += (u[j] > thr); eq += (u[j] == thr); }
    int gt_tot = __reduce_add_sync(FULL, gt);
    int extra = k - gt_tot;
    int eq_excl = iscan(eq, lane) - eq;
    int myq = extra - eq_excl;
    myq = myq < 0 ? 0 : (myq > eq ? eq : myq);
    int kc = gt + myq;
    int pos = iscan(kc, lane) - kc;
    int used = 0;
#pragma unroll
    for (int j = 0; j < NV; j++) {
        bool keep = (u[j] > thr);
        if (!keep && u[j] == thr && used < myq) { keep = true; used++; }
        if (keep) outrow[pos++] = tanh_fast(funkey(u[j]));
    }
}

// ---------------------------------------------------------------------------
// Kernel A: per-(batch, slice-group) CTA. grid = 512 * 4, block = 256.
// Covers rpp in [4*sgrp, 4*sgrp+4): emb rows [16sgrp,16sgrp+16),
// conv1-fold channels [64sgrp,64sgrp+64), conv2-fold channels same range.
// ---------------------------------------------------------------------------
__global__ void __launch_bounds__(NTHREADS, 4) dcnn_main(
    const int* __restrict__ x, const float* __restrict__ emb,
    const float* __restrict__ w1, const float* __restrict__ b1,
    const float* __restrict__ w2, const float* __restrict__ b2)
{
    extern __shared__ float sm[];
    float* sm_in = sm + OFF_IN;   // [16][269] padded embedded input slice
    float* sm_A  = sm + OFF_A;    // [64][140] padded layer-1 output slice

    const int tid = threadIdx.x, lane = tid & 31, wid = tid >> 5;
    const int b = blockIdx.x >> 2, sgrp = blockIdx.x & 3;

    // ---- Phase 0: zero smem (establishes conv zero-padding) ----
    for (int i = tid; i < SMEM_FLOATS; i += NTHREADS) sm[i] = 0.f;
    __syncthreads();

    // ---- Phase 1: embedding gather for this slice, transposed, padded by 6 ----
    const int* xb = x + b * S;
    const int dbase = 16 * sgrp;
    for (int i = tid; i < S * ROWS_IN; i += NTHREADS) {
        int s = i >> 4, dl = i & 15;
        sm_in[dl * STR1 + 6 + s] = emb[(long)xb[s] * 64 + dbase + dl];
    }
    __syncthreads();

    // ---- Phase 2: conv1 (K=7, groups) + fold(pairs) + top-131 + tanh ----
    // Association matches XLA: complete ascending-k chain per conv channel,
    // bias per channel, fold adds the two finished results.
#pragma unroll 1
    for (int cl = wid; cl < 64; cl += 8) {
        int ci = 64 * sgrp + cl;                    // global folded channel
        int rp = ci >> 3, f = ci & 7;
        int o0 = (2 * rp) * 8 + f, o1 = o0 + 8;
        float wA[7], wB[7];
#pragma unroll
        for (int k = 0; k < 7; k++) { wA[k] = w1[o0 * 7 + k]; wB[k] = w1[o1 * 7 + k]; }
        float bA = b1[o0], bB = b1[o1];
        const float* inA = sm_in + (2 * (cl >> 3)) * STR1;   // local emb rows
        const float* inB = inA + STR1;

        int t0 = lane * 9;                          // blocked: preserves index order
        float a[15], bb[15];
#pragma unroll
        for (int i = 0; i < 15; i++) {
            int idx = t0 + i; bool ok = idx < 268;
            a[i]  = ok ? inA[idx] : 0.f;
            bb[i] = ok ? inB[idx] : 0.f;
        }
        unsigned u[9];
#pragma unroll
        for (int j = 0; j < 9; j++) {
            float sA = 0.f, sB = 0.f;
#pragma unroll
            for (int k = 0; k < 7; k++) {           // two independent ascending chains
                sA = fmaf(wA[k], a[j + k], sA);
                sB = fmaf(wB[k], bb[j + k], sB);
            }
            float acc = (sA + bA) + (sB + bB);      // fold after completed channels
            u[j] = (t0 + j < L1_LEN) ? fkey(acc) : 0u;
        }
        topk_write_keys<9>(u, K1, sm_A + cl * STR2 + 4, lane);
    }
    __syncthreads();

    // ---- Phase 3: conv2 (K=5) + fold + top-4 + tanh ----
    // Thread-per-(channel, position-chunk): 64 channels x 4 chunks.
    {
        const int rpp_l = wid >> 1;                 // 0..3 local slice
        const int rpp   = 4 * sgrp + rpp_l;
        const int f2    = (wid & 1) * 8 + (lane >> 2);
        const int chunk = lane & 3;
        const int ci2   = rpp * 16 + f2;            // global conv2-fold channel
        const int o0    = (2 * rpp) * 16 + f2, o1 = o0 + 16;
        const float bA  = b2[o0], bB = b2[o1];
        const float* W0 = w2 + o0 * 40;
        const float* W1 = w2 + o1 * 40;
        const float* rows0 = sm_A + (16 * rpp_l) * STR2;
        const float* rows1 = rows0 + 8 * STR2;

        const int p0 = chunk * 34;
        const int np = (chunk == 3) ? 33 : 34;

        unsigned long long m0 = 0, m1 = 0, m2 = 0, m3 = 0;

#pragma unroll 1
        for (int pb = 0; pb < 34; pb += 7) {
            const int base = p0 + pb;
            const int nn = min(7, np - pb);
            float accA[7] = {0, 0, 0, 0, 0, 0, 0};
            float accB[7] = {0, 0, 0, 0, 0, 0, 0};
            float win[11];
#pragma unroll
            for (int i = 0; i < 8; i++) {           // channel A: (i asc, k2 asc) chain
                const float* row = rows0 + i * STR2;
#pragma unroll
                for (int q = 0; q < 10; q++) win[q] = row[base + q];
                win[10] = (base + 10 < STR2) ? row[base + 10] : 0.f;
#pragma unroll
                for (int k2 = 0; k2 < 5; k2++) {
                    float w = W0[i * 5 + k2];
#pragma unroll
                    for (int j = 0; j < 7; j++)
                        accA[j] = fmaf(w, win[j + k2], accA[j]);
                }
            }
#pragma unroll
            for (int i = 0; i < 8; i++) {           // channel B
                const float* row = rows1 + i * STR2;
#pragma unroll
                for (int q = 0; q < 10; q++) win[q] = row[base + q];
                win[10] = (base + 10 < STR2) ? row[base + 10] : 0.f;
#pragma unroll
                for (int k2 = 0; k2 < 5; k2++) {
                    float w = W1[i * 5 + k2];
#pragma unroll
                    for (int j = 0; j < 7; j++)
                        accB[j] = fmaf(w, win[j + k2], accB[j]);
                }
            }
#pragma unroll
            for (int j = 0; j < 7; j++) {
                if (j < nn) {
                    float r = (accA[j] + bA) + (accB[j] + bB);  // fold after channels
                    int p = base + j;
                    unsigned long long cand =
                        ((unsigned long long)fkey(r) << 32) | (unsigned)(~(unsigned)p);
                    if (cand > m3) {                 // sorted insert (desc)
                        m3 = cand;
                        if (m3 > m2) { unsigned long long t = m2; m2 = m3; m3 = t;
                            if (m2 > m1) { t = m1; m1 = m2; m2 = t;
                                if (m1 > m0) { t = m0; m0 = m1; m1 = t; } } }
                    }
                }
            }
        }

        // Merge the 4 chunk top-4 lists (desc sorted) -> channel top-4
#pragma unroll
        for (int d = 1; d <= 2; d <<= 1) {
            unsigned long long b0 = __shfl_xor_sync(FULL, m0, d);
            unsigned long long b1v = __shfl_xor_sync(FULL, m1, d);
            unsigned long long b2v = __shfl_xor_sync(FULL, m2, d);
            unsigned long long b3v = __shfl_xor_sync(FULL, m3, d);
            unsigned long long t0v = umax64(m0, b3v);
            unsigned long long t1v = umax64(m1, b2v);
            unsigned long long t2v = umax64(m2, b1v);
            unsigned long long t3v = umax64(m3, b0);
            unsigned long long s0 = umax64(t0v, t2v), s2 = umin64(t0v, t2v);
            unsigned long long s1 = umax64(t1v, t3v), s3 = umin64(t1v, t3v);
            m0 = umax64(s0, s1); m1 = umin64(s0, s1);
            m2 = umax64(s2, s3); m3 = umin64(s2, s3);
        }

        // Sort the 4 winners by original index (low32 = ~p: desc-by-low32 ==
        // ascending p). 5-CE network keyed on low 32 bits.
        {
            unsigned long long a0 = m0, a1 = m1, a2 = m2, a3 = m3, t;
            if ((unsigned)a0 < (unsigned)a1) { t = a0; a0 = a1; a1 = t; }
            if ((unsigned)a2 < (unsigned)a3) { t = a2; a2 = a3; a3 = t; }
            if ((unsigned)a0 < (unsigned)a2) { t = a0; a0 = a2; a2 = t; }
            if ((unsigned)a1 < (unsigned)a3) { t = a1; a1 = a3; a3 = t; }
            if ((unsigned)a1 < (unsigned)a2) { t = a1; a1 = a2; a2 = t; }
            unsigned long long sel = (chunk == 0) ? a0 : (chunk == 1) ? a1
                                   : (chunk == 2) ? a2 : a3;
            g_T2[b * 1024 + ci2 * 4 + chunk] = tanh_fast(funkey((unsigned)(sel >> 32)));
        }
    }
}

// ---------------------------------------------------------------------------
// Kernel B: FC (1024 -> 6) per batch. grid = 512, block = 192 (warp/class).
// ---------------------------------------------------------------------------
__global__ void __launch_bounds__(192) dcnn_fc(
    const float* __restrict__ fcw, const float* __restrict__ fcb,
    float* __restrict__ out)
{
    const int b = blockIdx.x, lane = threadIdx.x & 31, wid = threadIdx.x >> 5;
    const float* t2 = g_T2 + b * 1024;
    float s = 0.f;
    for (int d = lane; d < 1024; d += 32)
        s = fmaf(fcw[wid * 1024 + d], t2[d], s);
#pragma unroll
    for (int o = 16; o; o >>= 1) s += __shfl_xor_sync(FULL, s, o);
    if (lane == 0) out[b * 6 + wid] = s + fcb[wid];
}

extern "C" void kernel_launch(void* const* d_in, const int* in_sizes, int n_in,
                              void* d_out, int out_size) {
    const int*   x   = (const int*)d_in[0];
    const float* emb = (const float*)d_in[1];
    const float* w1  = (const float*)d_in[2];
    const float* b1  = (const float*)d_in[3];
    const float* w2  = (const float*)d_in[4];
    const float* b2  = (const float*)d_in[5];
    const float* fcw = (const float*)d_in[6];
    const float* fcb = (const float*)d_in[7];
    float* out = (float*)d_out;

    cudaFuncSetAttribute(dcnn_main, cudaFuncAttributeMaxDynamicSharedMemorySize, SMEM_BYTES);
    dcnn_main<<<512 * NCTA_PER_B, NTHREADS, SMEM_BYTES>>>(x, emb, w1, b1, w2, b2);
    dcnn_fc<<<512, 192>>>(fcw, fcb, out);
}